// round 11
// baseline (speedup 1.0000x reference)
#include <cuda_runtime.h>

#define NB        10000
#define VOCAB     10000
#define SEQ       80
#define EMB       100
#define UNITS     64
#define RPB       8           // rows per block -> grid = 1250 (single wave @ occ 9)
#define NTHREADS  64          // 2 warps; warp w owns k-half [w*32, w*32+32)
#define KP        16          // k-pairs per warp
#define RRED      4           // rows reduced per warp

// precomputed ETable[v][u] = emb[v] @ Wx[:,u] + b[u]
__device__ float g_etable[VOCAB * UNITS];

typedef unsigned long long u64;

__device__ __forceinline__ void fma2(u64& d, u64 a, u64 b) {
    asm("fma.rn.f32x2 %0, %1, %2, %0;" : "+l"(d) : "l"(a), "l"(b));
}
__device__ __forceinline__ u64 mul2(u64 a, u64 b) {
    u64 r; asm("mul.rn.f32x2 %0, %1, %2;" : "=l"(r) : "l"(a), "l"(b)); return r;
}
__device__ __forceinline__ u64 packf2(float lo, float hi) {
    u64 r; asm("mov.b64 %0, {%1, %2};" : "=l"(r) : "f"(lo), "f"(hi)); return r;
}
__device__ __forceinline__ float foldf(u64 v) {
    float lo, hi;
    asm("mov.b64 {%0, %1}, %2;" : "=f"(lo), "=f"(hi) : "l"(v));
    return lo + hi;
}
__device__ __forceinline__ float tanhx(float x) {
    float r; asm("tanh.approx.f32 %0, %1;" : "=f"(r) : "f"(x)); return r;
}

// ============ kernel 1: ETable = emb @ Wx + b (one-shot, 64M MACs) ============
__global__ __launch_bounds__(256)
void build_etable(const float* __restrict__ emb,
                  const float* __restrict__ Wx,
                  const float* __restrict__ bias)
{
    const int w = threadIdx.x >> 5, l = threadIdx.x & 31;
    const int row = blockIdx.x * 8 + w;      // 1250 * 8 = 10000 exact
    const int u = l * 2;
    float2 acc = make_float2(bias[u], bias[u + 1]);
    const float* er = emb + row * EMB;
    #pragma unroll 4
    for (int e = 0; e < EMB; ++e) {
        float xe = __ldg(er + e);
        float2 wv = *(const float2*)(Wx + e * UNITS + u);
        acc.x = fmaf(xe, wv.x, acc.x);
        acc.y = fmaf(xe, wv.y, acc.y);
    }
    *(float2*)(g_etable + row * UNITS + u) = acc;
}

// ===== kernel 2: 2-warp k-split, RPB=8, 9 blocks/SM, single wave =====
__global__ __launch_bounds__(NTHREADS, 9)
void rnn_scan(const int* __restrict__ tokens,
              const float* __restrict__ Wh,
              const float* __restrict__ Wfc,
              const float* __restrict__ bfc,
              float* __restrict__ out)
{
    __shared__ float  h_s[RPB][UNITS];          // 2048 B
    __shared__ float2 part_s[2][RPB][32];       // 4096 B: [warp][row][lane]
    __shared__ int    tok_s[SEQ][RPB];          // 2560 B (pre-scaled offsets)

    const int tid  = threadIdx.x;
    const int w    = tid >> 5;                  // warp: k-half owner
    const int l    = tid & 31;
    const int u0   = 2 * l;                     // units owned: u0, u0+1
    const int row0 = blockIdx.x * RPB;

    // ---- stage tokens (transposed [t][r]), pre-scaled to element offsets ----
    for (int i = tid; i < SEQ * RPB; i += NTHREADS) {
        int t = i >> 3, r = i & 7;
        tok_s[t][r] = tokens[(row0 + r) * SEQ + t] * UNITS;
    }
    // ---- zero h ----
    for (int i = tid; i < RPB * UNITS; i += NTHREADS)
        ((float*)h_s)[i] = 0.0f;

    // ---- this warp's k-half of Wh, k-paired, into 32 u64 registers ----
    u64 wu0[KP], wu1[KP];
    #pragma unroll
    for (int k2 = 0; k2 < KP; ++k2) {
        int kp = w * KP + k2;
        float2 a = *(const float2*)(Wh + (2 * kp)     * UNITS + u0);
        float2 b = *(const float2*)(Wh + (2 * kp + 1) * UNITS + u0);
        wu0[k2] = packf2(a.x, b.x);
        wu1[k2] = packf2(a.y, b.y);
    }
    __syncthreads();

    // ---- xp(0) for this warp's reduction rows (w*4 .. w*4+3) ----
    float2 xc[RRED];
    #pragma unroll
    for (int i = 0; i < RRED; ++i)
        xc[i] = *(const float2*)(g_etable + tok_s[0][w * RRED + i] + u0);

    for (int t = 0; t < SEQ; ++t) {
        // ---- partial h @ Wh over this warp's k-half ----
        u64 a0[RPB], a1[RPB];
        #pragma unroll
        for (int r = 0; r < RPB; ++r) {             // j = 0: init via MUL2
            ulonglong2 hv = *(const ulonglong2*)(&h_s[r][w * 32]);   // broadcast
            a0[r] = mul2(hv.x, wu0[0]);
            a1[r] = mul2(hv.x, wu1[0]);
            fma2(a0[r], hv.y, wu0[1]);
            fma2(a1[r], hv.y, wu1[1]);
        }
        #pragma unroll
        for (int j = 1; j < 8; ++j) {               // remaining 7 j-groups
            #pragma unroll
            for (int r = 0; r < RPB; ++r) {
                ulonglong2 hv = *(const ulonglong2*)(&h_s[r][w * 32 + 4 * j]);
                fma2(a0[r], hv.x, wu0[2 * j]);
                fma2(a1[r], hv.x, wu1[2 * j]);
                fma2(a0[r], hv.y, wu0[2 * j + 1]);
                fma2(a1[r], hv.y, wu1[2 * j + 1]);
            }
        }

        // ---- fold k-lane split in registers, publish float2 (STS.64) ----
        #pragma unroll
        for (int r = 0; r < RPB; ++r)
            part_s[w][r][l] = make_float2(foldf(a0[r]), foldf(a1[r]));
        __syncthreads();    // partials visible; all h reads of this step done

        // ---- reduce + tanh + write new h: warp w handles rows w*4..w*4+3 ----
        #pragma unroll
        for (int i = 0; i < RRED; ++i) {
            int r = w * RRED + i;
            float2 pa = part_s[0][r][l];
            float2 pb = part_s[1][r][l];
            float v0 = pa.x + pb.x + xc[i].x;
            float v1 = pa.y + pb.y + xc[i].y;
            *(u64*)(&h_s[r][u0]) = packf2(tanhx(v0), tanhx(v1));
        }

        // ---- reload xc for t+1 (covered by barrier + next compute phase) ----
        const int tn = (t + 1 < SEQ) ? (t + 1) : (SEQ - 1);
        #pragma unroll
        for (int i = 0; i < RRED; ++i)
            xc[i] = *(const float2*)(g_etable + tok_s[tn][w * RRED + i] + u0);

        __syncthreads();    // new h visible to both warps
    }

    // ---- final FC + sigmoid: threads 0..7 each handle one row ----
    if (tid < RPB) {
        const float* hf = h_s[tid];
        float dot = 0.0f;
        #pragma unroll 8
        for (int v = 0; v < UNITS; ++v) dot += hf[v] * __ldg(Wfc + v);
        float logit = dot + __ldg(bfc);
        out[row0 + tid] = 1.0f / (1.0f + __expf(-logit));
    }
}

extern "C" void kernel_launch(void* const* d_in, const int* in_sizes, int n_in,
                              void* d_out, int out_size) {
    const int*   tokens = (const int*)  d_in[0];
    const float* emb    = (const float*)d_in[1];
    const float* Wx     = (const float*)d_in[2];
    const float* Wh     = (const float*)d_in[3];
    const float* b      = (const float*)d_in[4];
    const float* Wfc    = (const float*)d_in[5];
    const float* bfc    = (const float*)d_in[6];
    float* out          = (float*)d_out;

    build_etable<<<VOCAB / 8, 256>>>(emb, Wx, b);
    rnn_scan<<<NB / RPB, NTHREADS>>>(tokens, Wh, Wfc, bfc, out);
}

// round 12
// speedup vs baseline: 1.0216x; 1.0216x over previous
#include <cuda_runtime.h>

#define NB        10000
#define VOCAB     10000
#define SEQ       80
#define EMB       100
#define UNITS     64
#define RPB       10          // rows per block -> grid = 1000 (single wave @ occ 7)
#define NTHREADS  64          // 2 warps; warp w owns k-half [w*32, w*32+32)
#define KP        16          // k-pairs per warp
#define RRED      5           // rows whose xp this warp folds in pre-publish

// precomputed ETable[v][u] = emb[v] @ Wx[:,u] + b[u]
__device__ float g_etable[VOCAB * UNITS];

typedef unsigned long long u64;

__device__ __forceinline__ void fma2(u64& d, u64 a, u64 b) {
    asm("fma.rn.f32x2 %0, %1, %2, %0;" : "+l"(d) : "l"(a), "l"(b));
}
__device__ __forceinline__ u64 mul2(u64 a, u64 b) {
    u64 r; asm("mul.rn.f32x2 %0, %1, %2;" : "=l"(r) : "l"(a), "l"(b)); return r;
}
__device__ __forceinline__ u64 packf2(float lo, float hi) {
    u64 r; asm("mov.b64 %0, {%1, %2};" : "=l"(r) : "f"(lo), "f"(hi)); return r;
}
__device__ __forceinline__ float foldf(u64 v) {
    float lo, hi;
    asm("mov.b64 {%0, %1}, %2;" : "=f"(lo), "=f"(hi) : "l"(v));
    return lo + hi;
}
__device__ __forceinline__ float tanhx(float x) {
    float r; asm("tanh.approx.f32 %0, %1;" : "=f"(r) : "f"(x)); return r;
}

// ============ kernel 1: ETable = emb @ Wx + b (one-shot, 64M MACs) ============
__global__ __launch_bounds__(256)
void build_etable(const float* __restrict__ emb,
                  const float* __restrict__ Wx,
                  const float* __restrict__ bias)
{
    const int w = threadIdx.x >> 5, l = threadIdx.x & 31;
    const int row = blockIdx.x * 8 + w;      // 1250 * 8 = 10000 exact
    const int u = l * 2;
    float2 acc = make_float2(bias[u], bias[u + 1]);
    const float* er = emb + row * EMB;
    #pragma unroll 4
    for (int e = 0; e < EMB; ++e) {
        float xe = __ldg(er + e);
        float2 wv = *(const float2*)(Wx + e * UNITS + u);
        acc.x = fmaf(xe, wv.x, acc.x);
        acc.y = fmaf(xe, wv.y, acc.y);
    }
    *(float2*)(g_etable + row * UNITS + u) = acc;
}

// ===== kernel 2: k-split, warp-private h, ONE barrier per step =====
__global__ __launch_bounds__(NTHREADS, 7)
void rnn_scan(const int* __restrict__ tokens,
              const float* __restrict__ Wh,
              const float* __restrict__ Wfc,
              const float* __restrict__ bfc,
              float* __restrict__ out)
{
    __shared__ float  h_s[2][RPB][UNITS];        // per-warp private h copies, 5120 B
    __shared__ float2 part_s[2][2][RPB][32];     // [buf][warp][row][lane], 10240 B
    __shared__ int    tok_s[SEQ][RPB];           // 3200 B (pre-scaled offsets)

    const int tid  = threadIdx.x;
    const int w    = tid >> 5;                   // warp: k-half owner
    const int l    = tid & 31;
    const int u0   = 2 * l;                      // units owned: u0, u0+1
    const int row0 = blockIdx.x * RPB;

    // ---- stage tokens (transposed [t][r]), pre-scaled to element offsets ----
    for (int i = tid; i < SEQ * RPB; i += NTHREADS) {
        int t = i / RPB, r = i - t * RPB;
        tok_s[t][r] = tokens[(row0 + r) * SEQ + t] * UNITS;
    }
    // ---- zero both private h copies ----
    for (int i = tid; i < 2 * RPB * UNITS; i += NTHREADS)
        ((float*)h_s)[i] = 0.0f;

    // ---- this warp's k-half of Wh, k-paired, into 32 u64 registers ----
    u64 wu0[KP], wu1[KP];
    #pragma unroll
    for (int k2 = 0; k2 < KP; ++k2) {
        int kp = w * KP + k2;
        float2 a = *(const float2*)(Wh + (2 * kp)     * UNITS + u0);
        float2 b = *(const float2*)(Wh + (2 * kp + 1) * UNITS + u0);
        wu0[k2] = packf2(a.x, b.x);
        wu1[k2] = packf2(a.y, b.y);
    }
    __syncthreads();

    // ---- xp(0) for this warp's designated rows (w*5 .. w*5+4) ----
    float2 xc[RRED];
    #pragma unroll
    for (int i = 0; i < RRED; ++i)
        xc[i] = *(const float2*)(g_etable + tok_s[0][w * RRED + i] + u0);

    const float (*hme)[UNITS] = h_s[w];          // own private h (read)
    float (*hwr)[UNITS] = h_s[w];                // own private h (write)

    for (int t = 0; t < SEQ; ++t) {
        const int buf = t & 1;

        // ---- partial h @ Wh over this warp's k-half (reads OWN h copy) ----
        u64 a0[RPB], a1[RPB];
        #pragma unroll
        for (int r = 0; r < RPB; ++r) {              // j = 0: init via MUL2
            ulonglong2 hv = *(const ulonglong2*)(&hme[r][w * 32]);   // broadcast
            a0[r] = mul2(hv.x, wu0[0]);
            a1[r] = mul2(hv.x, wu1[0]);
            fma2(a0[r], hv.y, wu0[1]);
            fma2(a1[r], hv.y, wu1[1]);
        }
        #pragma unroll
        for (int j = 1; j < 8; ++j) {                // remaining 7 j-groups
            #pragma unroll
            for (int r = 0; r < RPB; ++r) {
                ulonglong2 hv = *(const ulonglong2*)(&hme[r][w * 32 + 4 * j]);
                fma2(a0[r], hv.x, wu0[2 * j]);
                fma2(a1[r], hv.x, wu1[2 * j]);
                fma2(a0[r], hv.y, wu0[2 * j + 1]);
                fma2(a1[r], hv.y, wu1[2 * j + 1]);
            }
        }

        // ---- fold k-lane split; add xp to this warp's designated rows ----
        float2 fp[RPB];
        #pragma unroll
        for (int r = 0; r < RPB; ++r)
            fp[r] = make_float2(foldf(a0[r]), foldf(a1[r]));
        #pragma unroll
        for (int i = 0; i < RRED; ++i) {
            fp[w * RRED + i].x += xc[i].x;
            fp[w * RRED + i].y += xc[i].y;
        }

        // ---- publish own partial (keeps register copy), single barrier ----
        #pragma unroll
        for (int r = 0; r < RPB; ++r)
            part_s[buf][w][r][l] = fp[r];
        __syncthreads();

        // ---- reload xc for t+1 (latency covered by combine + next compute) ----
        const int tn = (t + 1 < SEQ) ? (t + 1) : (SEQ - 1);
        #pragma unroll
        for (int i = 0; i < RRED; ++i)
            xc[i] = *(const float2*)(g_etable + tok_s[tn][w * RRED + i] + u0);

        // ---- combine own regs + other warp's partial; write OWN h copy ----
        #pragma unroll
        for (int r = 0; r < RPB; ++r) {
            float2 po = part_s[buf][1 - w][r][l];
            float v0 = fp[r].x + po.x;
            float v1 = fp[r].y + po.y;
            *(u64*)(&hwr[r][u0]) = packf2(tanhx(v0), tanhx(v1));
        }
        // no second barrier: next compute reads only this warp's own writes;
        // part_s WAR across steps is covered by buffer alternation + the
        // next step's barrier.
    }

    // ---- final FC + sigmoid: warp 0, lanes 0..9 (reads warp-0's h copy) ----
    __syncwarp();
    if (w == 0 && l < RPB) {
        const float* hf = h_s[0][l];
        float dot = 0.0f;
        #pragma unroll 8
        for (int v = 0; v < UNITS; ++v) dot += hf[v] * __ldg(Wfc + v);
        float logit = dot + __ldg(bfc);
        out[row0 + l] = 1.0f / (1.0f + __expf(-logit));
    }
}

extern "C" void kernel_launch(void* const* d_in, const int* in_sizes, int n_in,
                              void* d_out, int out_size) {
    const int*   tokens = (const int*)  d_in[0];
    const float* emb    = (const float*)d_in[1];
    const float* Wx     = (const float*)d_in[2];
    const float* Wh     = (const float*)d_in[3];
    const float* b      = (const float*)d_in[4];
    const float* Wfc    = (const float*)d_in[5];
    const float* bfc    = (const float*)d_in[6];
    float* out          = (float*)d_out;

    build_etable<<<VOCAB / 8, 256>>>(emb, Wx, b);
    rnn_scan<<<NB / RPB, NTHREADS>>>(tokens, Wh, Wfc, bfc, out);
}

// round 13
// speedup vs baseline: 1.2997x; 1.2723x over previous
#include <cuda_runtime.h>

#define NB        10000
#define VOCAB     10000
#define SEQ       80
#define EMB       100
#define UNITS     64
#define RPB       9           // rows per block -> grid = 1112 (single wave @ occ 8)
#define GRID      ((NB + RPB - 1) / RPB)   // 1112
#define NTHREADS  64          // 2 warps; warp w owns k-half [w*32, w*32+32)
#define KP        16          // k-pairs per warp
#define RRED      5           // reduce rows: warp0 -> 0..4, warp1 -> 4..8 (overlap benign)

// precomputed ETable[v][u] = emb[v] @ Wx[:,u] + b[u]
__device__ float g_etable[VOCAB * UNITS];

typedef unsigned long long u64;

__device__ __forceinline__ void fma2(u64& d, u64 a, u64 b) {
    asm("fma.rn.f32x2 %0, %1, %2, %0;" : "+l"(d) : "l"(a), "l"(b));
}
__device__ __forceinline__ u64 mul2(u64 a, u64 b) {
    u64 r; asm("mul.rn.f32x2 %0, %1, %2;" : "=l"(r) : "l"(a), "l"(b)); return r;
}
__device__ __forceinline__ u64 packf2(float lo, float hi) {
    u64 r; asm("mov.b64 %0, {%1, %2};" : "=l"(r) : "f"(lo), "f"(hi)); return r;
}
__device__ __forceinline__ float foldf(u64 v) {
    float lo, hi;
    asm("mov.b64 {%0, %1}, %2;" : "=f"(lo), "=f"(hi) : "l"(v));
    return lo + hi;
}
__device__ __forceinline__ float tanhx(float x) {
    float r; asm("tanh.approx.f32 %0, %1;" : "=f"(r) : "f"(x)); return r;
}

// ============ kernel 1: ETable = emb @ Wx + b (one-shot, 64M MACs) ============
__global__ __launch_bounds__(256)
void build_etable(const float* __restrict__ emb,
                  const float* __restrict__ Wx,
                  const float* __restrict__ bias)
{
    const int w = threadIdx.x >> 5, l = threadIdx.x & 31;
    const int row = blockIdx.x * 8 + w;      // 1250 * 8 = 10000 exact
    const int u = l * 2;
    float2 acc = make_float2(bias[u], bias[u + 1]);
    const float* er = emb + row * EMB;
    #pragma unroll 4
    for (int e = 0; e < EMB; ++e) {
        float xe = __ldg(er + e);
        float2 wv = *(const float2*)(Wx + e * UNITS + u);
        acc.x = fmaf(xe, wv.x, acc.x);
        acc.y = fmaf(xe, wv.y, acc.y);
    }
    *(float2*)(g_etable + row * UNITS + u) = acc;
}

// ===== kernel 2: 2-warp k-split (R10 dataflow), RPB=9, occ 8, single wave =====
__global__ __launch_bounds__(NTHREADS, 8)
void rnn_scan(const int* __restrict__ tokens,
              const float* __restrict__ Wh,
              const float* __restrict__ Wfc,
              const float* __restrict__ bfc,
              float* __restrict__ out)
{
    __shared__ float  h_s[RPB][UNITS];          // 2304 B
    __shared__ float2 part_s[2][RPB][32];       // 4608 B: [warp][row][lane]
    __shared__ int    tok_s[SEQ][RPB];          // 2880 B (pre-scaled offsets)

    const int tid  = threadIdx.x;
    const int w    = tid >> 5;                  // warp: k-half owner
    const int l    = tid & 31;
    const int u0   = 2 * l;                     // units owned: u0, u0+1
    const int row0 = blockIdx.x * RPB;

    // ---- stage tokens (transposed [t][r]), clamped + pre-scaled ----
    for (int i = tid; i < SEQ * RPB; i += NTHREADS) {
        int t = i / RPB, r = i - t * RPB;
        int gr = row0 + r;
        if (gr >= NB) gr = NB - 1;              // clamp ragged tail
        tok_s[t][r] = tokens[gr * SEQ + t] * UNITS;
    }
    // ---- zero h ----
    for (int i = tid; i < RPB * UNITS; i += NTHREADS)
        ((float*)h_s)[i] = 0.0f;

    // ---- this warp's k-half of Wh, k-paired, into 32 u64 registers ----
    u64 wu0[KP], wu1[KP];
    #pragma unroll
    for (int k2 = 0; k2 < KP; ++k2) {
        int kp = w * KP + k2;
        float2 a = *(const float2*)(Wh + (2 * kp)     * UNITS + u0);
        float2 b = *(const float2*)(Wh + (2 * kp + 1) * UNITS + u0);
        wu0[k2] = packf2(a.x, b.x);
        wu1[k2] = packf2(a.y, b.y);
    }
    __syncthreads();

    // ---- xp(0) for this warp's reduce rows (w*4 .. w*4+4) ----
    const int rbase = w * 4;
    float2 xc[RRED];
    #pragma unroll
    for (int i = 0; i < RRED; ++i)
        xc[i] = *(const float2*)(g_etable + tok_s[0][rbase + i] + u0);

    for (int t = 0; t < SEQ; ++t) {
        // ---- partial h @ Wh over this warp's k-half ----
        u64 a0[RPB], a1[RPB];
        #pragma unroll
        for (int r = 0; r < RPB; ++r) {             // j = 0: init via MUL2
            ulonglong2 hv = *(const ulonglong2*)(&h_s[r][w * 32]);   // broadcast
            a0[r] = mul2(hv.x, wu0[0]);
            a1[r] = mul2(hv.x, wu1[0]);
            fma2(a0[r], hv.y, wu0[1]);
            fma2(a1[r], hv.y, wu1[1]);
        }
        #pragma unroll
        for (int j = 1; j < 8; ++j) {               // remaining 7 j-groups
            #pragma unroll
            for (int r = 0; r < RPB; ++r) {
                ulonglong2 hv = *(const ulonglong2*)(&h_s[r][w * 32 + 4 * j]);
                fma2(a0[r], hv.x, wu0[2 * j]);
                fma2(a1[r], hv.x, wu1[2 * j]);
                fma2(a0[r], hv.y, wu0[2 * j + 1]);
                fma2(a1[r], hv.y, wu1[2 * j + 1]);
            }
        }

        // ---- fold k-lane split in registers, publish float2 (STS.64) ----
        #pragma unroll
        for (int r = 0; r < RPB; ++r)
            part_s[w][r][l] = make_float2(foldf(a0[r]), foldf(a1[r]));
        __syncthreads();    // partials visible; all h reads of this step done

        // ---- reduce + tanh + write new h: warp w -> rows w*4 .. w*4+4 ----
        // (row 4 handled by both warps with identical values: benign)
        #pragma unroll
        for (int i = 0; i < RRED; ++i) {
            int r = rbase + i;
            float2 pa = part_s[0][r][l];
            float2 pb = part_s[1][r][l];
            float v0 = pa.x + pb.x + xc[i].x;
            float v1 = pa.y + pb.y + xc[i].y;
            *(u64*)(&h_s[r][u0]) = packf2(tanhx(v0), tanhx(v1));
        }

        // ---- reload xc for t+1 (covered by barrier + next compute phase) ----
        const int tn = (t + 1 < SEQ) ? (t + 1) : (SEQ - 1);
        #pragma unroll
        for (int i = 0; i < RRED; ++i)
            xc[i] = *(const float2*)(g_etable + tok_s[tn][rbase + i] + u0);

        __syncthreads();    // new h visible to both warps
    }

    // ---- final FC + sigmoid: threads 0..8 each handle one row ----
    if (tid < RPB && row0 + tid < NB) {
        const float* hf = h_s[tid];
        float dot = 0.0f;
        #pragma unroll 8
        for (int v = 0; v < UNITS; ++v) dot += hf[v] * __ldg(Wfc + v);
        float logit = dot + __ldg(bfc);
        out[row0 + tid] = 1.0f / (1.0f + __expf(-logit));
    }
}

extern "C" void kernel_launch(void* const* d_in, const int* in_sizes, int n_in,
                              void* d_out, int out_size) {
    const int*   tokens = (const int*)  d_in[0];
    const float* emb    = (const float*)d_in[1];
    const float* Wx     = (const float*)d_in[2];
    const float* Wh     = (const float*)d_in[3];
    const float* b      = (const float*)d_in[4];
    const float* Wfc    = (const float*)d_in[5];
    const float* bfc    = (const float*)d_in[6];
    float* out          = (float*)d_out;

    build_etable<<<VOCAB / 8, 256>>>(emb, Wx, b);
    rnn_scan<<<GRID, NTHREADS>>>(tokens, Wh, Wfc, bfc, out);
}